// round 14
// baseline (speedup 1.0000x reference)
#include <cuda_runtime.h>
#include <cuda_fp16.h>
#include <math.h>
#include <cstdint>
#include <string.h>

#define NTOT   131072
#define DIM    512
#define DATT   256
#define NHEAD  4
#define NCLS   53
#define NCLP   64
#define BAGSZ  16
#define NBAGS  8192

#define TM     64            // rows per block (4 bags); grid 2048
#define KC     64            // K chunk
#define NCHUNK (DIM / KC)    // 8
#define NSTAGE 2
#define A_STRIDE 144         // bytes/row (64 fp16 = 128 + 16 pad; 144/16=9 -> conflict-free)
#define B_STRIDE 528         // bytes/row (256 fp16 + 8 pad)

// stage layout (bytes): A 64*144=9216 | B 64*528=33792
#define STAGE_SZ 43008
#define A_OFF    0
#define B_OFF    9216
#define PIPE_SZ  (NSTAGE * STAGE_SZ)      // 86016

// union region [0, PIPE_SZ): pipeline -> Wc fp16 image (65536) post-GEMM
#define OFF_W2    PIPE_SZ                 // 4096
#define OFF_SS    (OFF_W2 + 4096)         // 1024
#define OFF_WR    (OFF_SS + 1024)         // 256
#define OFF_REPR  (OFF_WR + 256)          // 8192 (4 bags x 512 f32)
#define OFF_PART  (OFF_REPR + 8192)       // 8192 (8 segs x 4 bags x 64 cls f32)
#define SMEM_TOTAL (OFF_PART + 8192)      // 107776 -> 2 CTAs/SM

__device__ __align__(16) __half g_Wpk[DIM * DATT];     // W1 fp16, k-major
__device__ __align__(16) __half g_Wc16[DIM * NCLP];    // Wc fp16, [k][64] padded

extern __shared__ char smem_raw[];

__device__ __forceinline__ uint32_t smem_u32(const void* p) {
    uint32_t a;
    asm("{ .reg .u64 t; cvta.to.shared.u64 t, %1; cvt.u32.u64 %0, t; }" : "=r"(a) : "l"(p));
    return a;
}
// L1-bypass (L2 -> smem) 16B async copy
__device__ __forceinline__ void cp16cg(uint32_t dst, const void* src) {
    asm volatile("cp.async.cg.shared.global [%0], [%1], 16;" :: "r"(dst), "l"(src));
}
#define CP_COMMIT() asm volatile("cp.async.commit_group;" ::: "memory")
#define CP_WAIT0()  asm volatile("cp.async.wait_group 0;" ::: "memory")

__device__ __forceinline__ void ldsm_x4(uint32_t* r, uint32_t addr) {
    asm volatile("ldmatrix.sync.aligned.m8n8.x4.shared.b16 {%0,%1,%2,%3}, [%4];"
        : "=r"(r[0]), "=r"(r[1]), "=r"(r[2]), "=r"(r[3]) : "r"(addr));
}
__device__ __forceinline__ void ldsm_x4_t(uint32_t* r, uint32_t addr) {
    asm volatile("ldmatrix.sync.aligned.m8n8.x4.trans.shared.b16 {%0,%1,%2,%3}, [%4];"
        : "=r"(r[0]), "=r"(r[1]), "=r"(r[2]), "=r"(r[3]) : "r"(addr));
}
__device__ __forceinline__ void mma16816(float* d, const uint32_t* a,
                                         uint32_t b0, uint32_t b1) {
    asm volatile(
        "mma.sync.aligned.m16n8k16.row.col.f32.f16.f16.f32 "
        "{%0,%1,%2,%3}, {%4,%5,%6,%7}, {%8,%9}, {%0,%1,%2,%3};"
        : "+f"(d[0]), "+f"(d[1]), "+f"(d[2]), "+f"(d[3])
        : "r"(a[0]), "r"(a[1]), "r"(a[2]), "r"(a[3]), "r"(b0), "r"(b1));
}

__device__ __forceinline__ float fast_tanh(float v) {
    const float a = fabsf(v);
    const float e = __expf(-2.0f * a);
    const float t = (1.0f - e) * __frcp_rn(1.0f + e);
    return copysignf(t, v);
}

// merged one-time prep
__global__ void prep_kernel(const float* __restrict__ W1, const float* __restrict__ Wc) {
    if (blockIdx.x < 512) {
        const int idx = blockIdx.x * 256 + threadIdx.x;
        g_Wpk[idx] = __float2half(W1[idx]);
    } else {
        const int idx = (blockIdx.x - 512) * 256 + threadIdx.x;
        const int k = idx >> 6, c = idx & 63;
        g_Wc16[idx] = (c < NCLS) ? __float2half(Wc[k * NCLS + c]) : __float2half(0.f);
    }
}

// B chunk: 64 k-rows x 512 B = 2048 x 16B transfers -> 8/thread
__device__ __forceinline__ void issue_b(int c, uint32_t sbase, int tid) {
    const uint32_t dst0 = sbase + (c & 1) * STAGE_SZ + B_OFF;
    const __half* src0 = g_Wpk + (size_t)c * (KC * DATT);
    #pragma unroll
    for (int it = 0; it < 8; it++) {
        const int q = it * 256 + tid;
        const int row = q >> 5, seg = q & 31;
        cp16cg(dst0 + row * B_STRIDE + seg * 16, src0 + row * DATT + seg * 8);
    }
    CP_COMMIT();
}

// A chunk: thread owns 16 consecutive floats of one row (row = tid>>2, colgrp = tid&3)
__device__ __forceinline__ void ld_a(const float* __restrict__ x, int row0,
                                     int c, int tid, float4* v) {
    const int row = tid >> 2, cg = tid & 3;
    const float* src = x + (size_t)(row0 + row) * DIM + c * KC + cg * 16;
    v[0] = *(const float4*)src;
    v[1] = *(const float4*)(src + 4);
    v[2] = *(const float4*)(src + 8);
    v[3] = *(const float4*)(src + 12);
}
__device__ __forceinline__ void st_a(int c, uint32_t sbase, int tid, const float4* v) {
    const int row = tid >> 2, cg = tid & 3;
    const uint32_t base = sbase + (c & 1) * STAGE_SZ + A_OFF + row * A_STRIDE + cg * 32;
    uint32_t hv[8];
    #pragma unroll
    for (int i = 0; i < 4; i++) {
        __half h0 = __float2half(v[i].x), h1 = __float2half(v[i].y);
        __half h2 = __float2half(v[i].z), h3 = __float2half(v[i].w);
        hv[i * 2 + 0] = (uint32_t)__half_as_ushort(h0) | ((uint32_t)__half_as_ushort(h1) << 16);
        hv[i * 2 + 1] = (uint32_t)__half_as_ushort(h2) | ((uint32_t)__half_as_ushort(h3) << 16);
    }
    asm volatile("st.shared.v4.b32 [%0], {%1,%2,%3,%4};" ::
        "r"(base), "r"(hv[0]), "r"(hv[1]), "r"(hv[2]), "r"(hv[3]));
    asm volatile("st.shared.v4.b32 [%0], {%1,%2,%3,%4};" ::
        "r"(base + 16), "r"(hv[4]), "r"(hv[5]), "r"(hv[6]), "r"(hv[7]));
}

__global__ __launch_bounds__(256, 2)
void mlssa_main(const float* __restrict__ x, const float* __restrict__ W2,
                const float* __restrict__ bc, float* __restrict__ out)
{
    const int tid  = threadIdx.x;
    const int wid  = tid >> 5;
    const int lane = tid & 31;
    const int row0 = blockIdx.x * TM;
    const uint32_t sbase = smem_u32(smem_raw);

    __half* wch  = (__half*)(smem_raw);           // overlays pipeline post-GEMM
    float*  w2s  = (float*)(smem_raw + OFF_W2);
    float*  ss   = (float*)(smem_raw + OFF_SS);
    float*  wr   = (float*)(smem_raw + OFF_WR);
    float*  repr = (float*)(smem_raw + OFF_REPR);
    float*  part = (float*)(smem_raw + OFF_PART);

    // prologue: stage chunk 0 into stage 0
    issue_b(0, sbase, tid);
    {
        float4 a0[4];
        ld_a(x, row0, 0, tid, a0);
        st_a(0, sbase, tid, a0);
    }

    for (int i = tid; i < DATT * NHEAD; i += 256) w2s[i] = W2[i];
    ss[tid] = 0.0f;

    const int warp_m = wid >> 2;   // 2(M) x 4(N), warp tile 32x64
    const int warp_n = wid & 3;

    const uint32_t aoff = (uint32_t)(warp_m * 32 + (lane & 15)) * A_STRIDE
                        + (uint32_t)(lane >> 4) * 16;
    const uint32_t boff = (uint32_t)(((lane >> 3) & 1) * 8 + (lane & 7)) * B_STRIDE
                        + (uint32_t)(warp_n * 64 + (lane >> 4) * 8) * 2;

    float acc[2][8][4];
    #pragma unroll
    for (int i = 0; i < 2; i++)
        #pragma unroll
        for (int j = 0; j < 8; j++)
            #pragma unroll
            for (int k = 0; k < 4; k++) acc[i][j][k] = 0.0f;

    for (int c = 0; c < NCHUNK; c++) {
        CP_WAIT0();
        __syncthreads();   // chunk c staged everywhere; other stage fully consumed

        float4 rA[4];
        if (c + 1 < NCHUNK) {
            ld_a(x, row0, c + 1, tid, rA);   // DRAM latency covered by mma body
            issue_b(c + 1, sbase, tid);      // into freed stage (c+1)&1
        }

        const uint32_t stg = sbase + (c & 1) * STAGE_SZ;
        const uint32_t sA = stg + A_OFF + aoff;
        const uint32_t sB = stg + B_OFF + boff;

        #pragma unroll
        for (int ks = 0; ks < 4; ks++) {
            uint32_t afr[2][4];
            ldsm_x4(afr[0], sA + ks * 32);
            ldsm_x4(afr[1], sA + 16 * A_STRIDE + ks * 32);
            #pragma unroll
            for (int g = 0; g < 4; g++) {
                uint32_t bfr[4];
                ldsm_x4_t(bfr, sB + ks * 16 * B_STRIDE + g * 32);
                #pragma unroll
                for (int mi = 0; mi < 2; mi++) {
                    mma16816(acc[mi][g * 2 + 0], afr[mi], bfr[0], bfr[1]);
                    mma16816(acc[mi][g * 2 + 1], afr[mi], bfr[2], bfr[3]);
                }
            }
        }

        if (c + 1 < NCHUNK)
            st_a(c + 1, sbase, tid, rA);     // stage (c+1)&1; consumed after next sync
    }

    // ---- fragment-direct epilogue: tanh + W2 projection in registers ----
    {
        float sp[4][4];
        #pragma unroll
        for (int i = 0; i < 4; i++)
            #pragma unroll
            for (int h = 0; h < 4; h++) sp[i][h] = 0.0f;

        const int cb0 = warp_n * 64 + (lane & 3) * 2;
        #pragma unroll
        for (int nj = 0; nj < 8; nj++) {
            const float4 wv0 = *(const float4*)&w2s[(cb0 + nj * 8) * 4];
            const float4 wv1 = *(const float4*)&w2s[(cb0 + nj * 8 + 1) * 4];
            #pragma unroll
            for (int mi = 0; mi < 2; mi++) {
                const float t0 = fast_tanh(acc[mi][nj][0]);
                const float t1 = fast_tanh(acc[mi][nj][1]);
                const float t2 = fast_tanh(acc[mi][nj][2]);
                const float t3 = fast_tanh(acc[mi][nj][3]);
                sp[mi*2+0][0] += t0 * wv0.x + t1 * wv1.x;
                sp[mi*2+0][1] += t0 * wv0.y + t1 * wv1.y;
                sp[mi*2+0][2] += t0 * wv0.z + t1 * wv1.z;
                sp[mi*2+0][3] += t0 * wv0.w + t1 * wv1.w;
                sp[mi*2+1][0] += t2 * wv0.x + t3 * wv1.x;
                sp[mi*2+1][1] += t2 * wv0.y + t3 * wv1.y;
                sp[mi*2+1][2] += t2 * wv0.z + t3 * wv1.z;
                sp[mi*2+1][3] += t2 * wv0.w + t3 * wv1.w;
            }
        }
        #pragma unroll
        for (int i = 0; i < 4; i++)
            #pragma unroll
            for (int h = 0; h < 4; h++) {
                sp[i][h] += __shfl_xor_sync(0xFFFFFFFF, sp[i][h], 1);
                sp[i][h] += __shfl_xor_sync(0xFFFFFFFF, sp[i][h], 2);
            }
        if ((lane & 3) == 0) {
            const int rbase = warp_m * 32 + (lane >> 2);
            #pragma unroll
            for (int i = 0; i < 4; i++) {
                const int row = rbase + ((i & 1) ? 8 : 0) + ((i >> 1) ? 16 : 0);
                #pragma unroll
                for (int h = 0; h < 4; h++)
                    atomicAdd(&ss[row * 4 + h], sp[i][h]);
            }
        }
    }
    __syncthreads();   // scores complete; pipeline region dead

    // kick Wc fp16 image into smem (overlaps softmax + pooling)
    {
        #pragma unroll
        for (int it = 0; it < 16; it++) {
            const int q = it * 256 + tid;              // 4096 x 16B
            const int row = q >> 3, seg = q & 7;
            cp16cg(sbase + row * 128 + seg * 16, g_Wc16 + (size_t)row * NCLP + seg * 8);
        }
        CP_COMMIT();
    }

    // per-bag softmax: thread = (row, head)
    {
        const int r = tid >> 2;
        const int h = tid & 3;
        const int b0 = r & ~15;
        float m = -1e30f;
        #pragma unroll
        for (int q = 0; q < BAGSZ; q++) m = fmaxf(m, ss[(b0 + q) * 4 + h]);
        float den = 0.f;
        #pragma unroll
        for (int q = 0; q < BAGSZ; q++) den += __expf(ss[(b0 + q) * 4 + h] - m);
        float a = __expf(ss[r * 4 + h] - m) * __frcp_rn(den);
        a += __shfl_xor_sync(0xFFFFFFFF, a, 1);
        a += __shfl_xor_sync(0xFFFFFFFF, a, 2);
        if (h == 0) wr[r] = a * 0.25f;
    }
    __syncthreads();

    // pooling: thread owns (bag, 8-dim block)
    {
        const int bag = tid >> 6;
        const int d0  = (tid & 63) * 8;
        float a0 = 0.f, a1 = 0.f, a2 = 0.f, a3 = 0.f;
        float a4 = 0.f, a5 = 0.f, a6 = 0.f, a7 = 0.f;
        #pragma unroll 4
        for (int q = 0; q < BAGSZ; q++) {
            const int rr = bag * BAGSZ + q;
            const float w = wr[rr];
            const float* src = x + (size_t)(row0 + rr) * DIM + d0;
            const float4 v0 = *(const float4*)src;
            const float4 v1 = *(const float4*)(src + 4);
            a0 += w * v0.x; a1 += w * v0.y; a2 += w * v0.z; a3 += w * v0.w;
            a4 += w * v1.x; a5 += w * v1.y; a6 += w * v1.z; a7 += w * v1.w;
        }
        *(float4*)&repr[bag * DIM + d0]     = make_float4(a0, a1, a2, a3);
        *(float4*)&repr[bag * DIM + d0 + 4] = make_float4(a4, a5, a6, a7);
    }
    CP_WAIT0();
    __syncthreads();   // repr + wch ready

    // classifier: thread owns 2 classes x 64-k segment x 4 bags
    {
        const int cls2 = (tid & 31) * 2;
        const int seg  = tid >> 5;
        float b0a = 0.f, b0b = 0.f, b1a = 0.f, b1b = 0.f;
        float b2a = 0.f, b2b = 0.f, b3a = 0.f, b3b = 0.f;
        const int k0 = seg * 64;
        #pragma unroll 8
        for (int k = 0; k < 64; k++) {
            const __half2 wv = *(const __half2*)&wch[(k0 + k) * NCLP + cls2];
            const float wa = __half2float(__low2half(wv));
            const float wb = __half2float(__high2half(wv));
            const float r0 = repr[0 * DIM + k0 + k];
            const float r1 = repr[1 * DIM + k0 + k];
            const float r2 = repr[2 * DIM + k0 + k];
            const float r3 = repr[3 * DIM + k0 + k];
            b0a += r0 * wa; b0b += r0 * wb;
            b1a += r1 * wa; b1b += r1 * wb;
            b2a += r2 * wa; b2b += r2 * wb;
            b3a += r3 * wa; b3b += r3 * wb;
        }
        float* p = part + seg * 256;
        p[0 * 64 + cls2] = b0a; p[0 * 64 + cls2 + 1] = b0b;
        p[1 * 64 + cls2] = b1a; p[1 * 64 + cls2 + 1] = b1b;
        p[2 * 64 + cls2] = b2a; p[2 * 64 + cls2 + 1] = b2b;
        p[3 * 64 + cls2] = b3a; p[3 * 64 + cls2 + 1] = b3b;
    }
    __syncthreads();

    // reduce 8 segments, add bias, store
    {
        const int bag = tid >> 6;
        const int cls = tid & 63;
        if (cls < NCLS) {
            float s = 0.f;
            #pragma unroll
            for (int g = 0; g < 8; g++) s += part[g * 256 + bag * 64 + cls];
            const int bag_g = blockIdx.x * (TM / BAGSZ) + bag;
            out[(size_t)bag_g * NCLS + cls] = s + bc[cls];
        }
    }
}

extern "C" void kernel_launch(void* const* d_in, const int* in_sizes, int n_in,
                              void* d_out, int out_size)
{
    const float* x  = (const float*)d_in[0];
    const float* W1 = (const float*)d_in[1];
    const float* W2 = (const float*)d_in[2];
    const float* Wc = (const float*)d_in[3];
    const float* bc = (const float*)d_in[4];
    float* out = (float*)d_out;

    cudaFuncSetAttribute(mlssa_main,
                         cudaFuncAttributeMaxDynamicSharedMemorySize, SMEM_TOTAL);

    prep_kernel<<<640, 256>>>(W1, Wc);
    mlssa_main<<<NTOT / TM, 256, SMEM_TOTAL>>>(x, W2, bc, out);
}

// round 15
// speedup vs baseline: 1.0886x; 1.0886x over previous
#include <cuda_runtime.h>
#include <cuda_fp16.h>
#include <math.h>
#include <cstdint>
#include <string.h>

#define NTOT   131072
#define DIM    512
#define DATT   256
#define NHEAD  4
#define NCLS   53
#define NCLP   64
#define BAGSZ  16
#define NBAGS  8192

#define TM     64            // rows per block (4 bags); grid 2048
#define KC     32            // K chunk
#define NCHUNK (DIM / KC)    // 16
#define NSTAGE 4
#define A_STRIDE 80          // bytes/row (32 fp16 + 8 pad)
#define B_STRIDE 528         // bytes/row (256 fp16 + 8 pad)

// stage layout (bytes): A 64*80=5120 | B 32*528=16896
#define STAGE_SZ 22016
#define A_OFF    0
#define B_OFF    5120
#define PIPE_SZ  (NSTAGE * STAGE_SZ)      // 88064

// union region [0, PIPE_SZ): pipeline -> Wc fp16 image (65536) post-GEMM
#define OFF_W2    PIPE_SZ                 // 4096
#define OFF_SS    (OFF_W2 + 4096)         // 1024
#define OFF_WR    (OFF_SS + 1024)         // 256
#define OFF_REPR  (OFF_WR + 256)          // 8192 (4 bags x 512 f32)
#define OFF_PART  (OFF_REPR + 8192)       // 8192 (8 segs x 4 bags x 64 cls f32)
#define SMEM_TOTAL (OFF_PART + 8192)      // 109824 -> 2 CTAs/SM

__device__ __align__(16) __half g_Wpk[DIM * DATT];     // W1 fp16, k-major
__device__ __align__(16) __half g_Wc16[DIM * NCLP];    // Wc fp16, [k][64] padded

extern __shared__ char smem_raw[];

__device__ __forceinline__ uint32_t smem_u32(const void* p) {
    uint32_t a;
    asm("{ .reg .u64 t; cvta.to.shared.u64 t, %1; cvt.u32.u64 %0, t; }" : "=r"(a) : "l"(p));
    return a;
}
// L1-bypass (L2 -> smem) 16B async copy
__device__ __forceinline__ void cp16cg(uint32_t dst, const void* src) {
    asm volatile("cp.async.cg.shared.global [%0], [%1], 16;" :: "r"(dst), "l"(src));
}
#define CP_COMMIT() asm volatile("cp.async.commit_group;" ::: "memory")
#define CP_WAIT2()  asm volatile("cp.async.wait_group 2;" ::: "memory")
#define CP_WAIT1()  asm volatile("cp.async.wait_group 1;" ::: "memory")
#define CP_WAIT0()  asm volatile("cp.async.wait_group 0;" ::: "memory")

__device__ __forceinline__ void ldsm_x4(uint32_t* r, uint32_t addr) {
    asm volatile("ldmatrix.sync.aligned.m8n8.x4.shared.b16 {%0,%1,%2,%3}, [%4];"
        : "=r"(r[0]), "=r"(r[1]), "=r"(r[2]), "=r"(r[3]) : "r"(addr));
}
__device__ __forceinline__ void ldsm_x4_t(uint32_t* r, uint32_t addr) {
    asm volatile("ldmatrix.sync.aligned.m8n8.x4.trans.shared.b16 {%0,%1,%2,%3}, [%4];"
        : "=r"(r[0]), "=r"(r[1]), "=r"(r[2]), "=r"(r[3]) : "r"(addr));
}
__device__ __forceinline__ void mma16816(float* d, const uint32_t* a,
                                         uint32_t b0, uint32_t b1) {
    asm volatile(
        "mma.sync.aligned.m16n8k16.row.col.f32.f16.f16.f32 "
        "{%0,%1,%2,%3}, {%4,%5,%6,%7}, {%8,%9}, {%0,%1,%2,%3};"
        : "+f"(d[0]), "+f"(d[1]), "+f"(d[2]), "+f"(d[3])
        : "r"(a[0]), "r"(a[1]), "r"(a[2]), "r"(a[3]), "r"(b0), "r"(b1));
}

__device__ __forceinline__ float fast_tanh(float v) {
    const float a = fabsf(v);
    const float e = __expf(-2.0f * a);
    const float t = (1.0f - e) * __frcp_rn(1.0f + e);
    return copysignf(t, v);
}

// merged one-time prep
__global__ void prep_kernel(const float* __restrict__ W1, const float* __restrict__ Wc) {
    if (blockIdx.x < 512) {
        const int idx = blockIdx.x * 256 + threadIdx.x;
        g_Wpk[idx] = __float2half(W1[idx]);
    } else {
        const int idx = (blockIdx.x - 512) * 256 + threadIdx.x;
        const int k = idx >> 6, c = idx & 63;
        g_Wc16[idx] = (c < NCLS) ? __float2half(Wc[k * NCLS + c]) : __float2half(0.f);
    }
}

__device__ __forceinline__ void issue_b(int c, uint32_t sbase, int tid) {
    const uint32_t dst0 = sbase + (c & (NSTAGE - 1)) * STAGE_SZ + B_OFF;
    const __half* src0 = g_Wpk + (size_t)c * (KC * DATT);
    #pragma unroll
    for (int it = 0; it < 4; it++) {
        const int q = it * 256 + tid;
        const int row = q >> 5, seg = q & 31;
        cp16cg(dst0 + row * B_STRIDE + seg * 16, src0 + row * DATT + seg * 8);
    }
    CP_COMMIT();
}

__device__ __forceinline__ void ld_a(const float* __restrict__ x, int row0,
                                     int c, int tid, float4& v0, float4& v1) {
    const int row = tid >> 2, cg = tid & 3;
    const float* src = x + (size_t)(row0 + row) * DIM + c * KC + cg * 8;
    v0 = *(const float4*)src;
    v1 = *(const float4*)(src + 4);
}
__device__ __forceinline__ void st_a(int c, uint32_t sbase, int tid,
                                     float4 v0, float4 v1) {
    const int row = tid >> 2, cg = tid & 3;
    const uint32_t base = sbase + (c & (NSTAGE - 1)) * STAGE_SZ + A_OFF
                        + row * A_STRIDE + cg * 16;
    __half h0 = __float2half(v0.x), h1 = __float2half(v0.y);
    __half h2 = __float2half(v0.z), h3 = __float2half(v0.w);
    __half h4 = __float2half(v1.x), h5 = __float2half(v1.y);
    __half h6 = __float2half(v1.z), h7 = __float2half(v1.w);
    uint4 hv = make_uint4(
        (uint32_t)__half_as_ushort(h0) | ((uint32_t)__half_as_ushort(h1) << 16),
        (uint32_t)__half_as_ushort(h2) | ((uint32_t)__half_as_ushort(h3) << 16),
        (uint32_t)__half_as_ushort(h4) | ((uint32_t)__half_as_ushort(h5) << 16),
        (uint32_t)__half_as_ushort(h6) | ((uint32_t)__half_as_ushort(h7) << 16));
    asm volatile("st.shared.v4.b32 [%0], {%1,%2,%3,%4};" ::
        "r"(base), "r"(hv.x), "r"(hv.y), "r"(hv.z), "r"(hv.w));
}

__global__ __launch_bounds__(256, 2)
void mlssa_main(const float* __restrict__ x, const float* __restrict__ W2,
                const float* __restrict__ bc, float* __restrict__ out)
{
    const int tid  = threadIdx.x;
    const int wid  = tid >> 5;
    const int lane = tid & 31;
    const int row0 = blockIdx.x * TM;
    const uint32_t sbase = smem_u32(smem_raw);

    __half* wch  = (__half*)(smem_raw);           // overlays pipeline post-GEMM
    float*  w2s  = (float*)(smem_raw + OFF_W2);
    float*  ss   = (float*)(smem_raw + OFF_SS);
    float*  wr   = (float*)(smem_raw + OFF_WR);
    float*  repr = (float*)(smem_raw + OFF_REPR);
    float*  part = (float*)(smem_raw + OFF_PART);

    // prologue: stage chunks 0..2; prefetch chunk 3 into regs
    issue_b(0, sbase, tid);
    issue_b(1, sbase, tid);
    issue_b(2, sbase, tid);
    {
        float4 a0, a1;
        ld_a(x, row0, 0, tid, a0, a1); st_a(0, sbase, tid, a0, a1);
        ld_a(x, row0, 1, tid, a0, a1); st_a(1, sbase, tid, a0, a1);
        ld_a(x, row0, 2, tid, a0, a1); st_a(2, sbase, tid, a0, a1);
    }
    float4 rA0, rA1;
    ld_a(x, row0, 3, tid, rA0, rA1);

    for (int i = tid; i < DATT * NHEAD; i += 256) w2s[i] = W2[i];
    ss[tid] = 0.0f;

    const int warp_m = wid >> 2;   // 2(M) x 4(N), warp tile 32x64
    const int warp_n = wid & 3;

    const uint32_t aoff = (uint32_t)(warp_m * 32 + (lane & 15)) * A_STRIDE
                        + (uint32_t)(lane >> 4) * 16;
    const uint32_t boff = (uint32_t)(((lane >> 3) & 1) * 8 + (lane & 7)) * B_STRIDE
                        + (uint32_t)(warp_n * 64 + (lane >> 4) * 8) * 2;

    float acc[2][8][4];
    #pragma unroll
    for (int i = 0; i < 2; i++)
        #pragma unroll
        for (int j = 0; j < 8; j++)
            #pragma unroll
            for (int k = 0; k < 4; k++) acc[i][j][k] = 0.0f;

    for (int c = 0; c < NCHUNK; c++) {
        if (c < NCHUNK - 2)       { CP_WAIT2(); }
        else if (c == NCHUNK - 2) { CP_WAIT1(); }
        else                      { CP_WAIT0(); }
        __syncthreads();   // chunk c visible; stage (c+3)&3 dead

        if (c + 3 < NCHUNK) {
            st_a(c + 3, sbase, tid, rA0, rA1);
            issue_b(c + 3, sbase, tid);
            if (c + 4 < NCHUNK) ld_a(x, row0, c + 4, tid, rA0, rA1);
        }

        const uint32_t stg = sbase + (c & (NSTAGE - 1)) * STAGE_SZ;
        const uint32_t sA = stg + A_OFF + aoff;
        const uint32_t sB = stg + B_OFF + boff;

        #pragma unroll
        for (int ks = 0; ks < 2; ks++) {
            uint32_t afr[2][4];
            ldsm_x4(afr[0], sA + ks * 32);
            ldsm_x4(afr[1], sA + 16 * A_STRIDE + ks * 32);
            #pragma unroll
            for (int g = 0; g < 4; g++) {
                uint32_t bfr[4];
                ldsm_x4_t(bfr, sB + ks * 16 * B_STRIDE + g * 32);
                #pragma unroll
                for (int mi = 0; mi < 2; mi++) {
                    mma16816(acc[mi][g * 2 + 0], afr[mi], bfr[0], bfr[1]);
                    mma16816(acc[mi][g * 2 + 1], afr[mi], bfr[2], bfr[3]);
                }
            }
        }
    }

    // ---- fragment-direct epilogue: tanh + W2 projection in registers ----
    {
        float sp[4][4];
        #pragma unroll
        for (int i = 0; i < 4; i++)
            #pragma unroll
            for (int h = 0; h < 4; h++) sp[i][h] = 0.0f;

        const int cb0 = warp_n * 64 + (lane & 3) * 2;
        #pragma unroll
        for (int nj = 0; nj < 8; nj++) {
            const float4 wv0 = *(const float4*)&w2s[(cb0 + nj * 8) * 4];
            const float4 wv1 = *(const float4*)&w2s[(cb0 + nj * 8 + 1) * 4];
            #pragma unroll
            for (int mi = 0; mi < 2; mi++) {
                const float t0 = fast_tanh(acc[mi][nj][0]);
                const float t1 = fast_tanh(acc[mi][nj][1]);
                const float t2 = fast_tanh(acc[mi][nj][2]);
                const float t3 = fast_tanh(acc[mi][nj][3]);
                sp[mi*2+0][0] += t0 * wv0.x + t1 * wv1.x;
                sp[mi*2+0][1] += t0 * wv0.y + t1 * wv1.y;
                sp[mi*2+0][2] += t0 * wv0.z + t1 * wv1.z;
                sp[mi*2+0][3] += t0 * wv0.w + t1 * wv1.w;
                sp[mi*2+1][0] += t2 * wv0.x + t3 * wv1.x;
                sp[mi*2+1][1] += t2 * wv0.y + t3 * wv1.y;
                sp[mi*2+1][2] += t2 * wv0.z + t3 * wv1.z;
                sp[mi*2+1][3] += t2 * wv0.w + t3 * wv1.w;
            }
        }
        #pragma unroll
        for (int i = 0; i < 4; i++)
            #pragma unroll
            for (int h = 0; h < 4; h++) {
                sp[i][h] += __shfl_xor_sync(0xFFFFFFFF, sp[i][h], 1);
                sp[i][h] += __shfl_xor_sync(0xFFFFFFFF, sp[i][h], 2);
            }
        if ((lane & 3) == 0) {
            const int rbase = warp_m * 32 + (lane >> 2);
            #pragma unroll
            for (int i = 0; i < 4; i++) {
                const int row = rbase + ((i & 1) ? 8 : 0) + ((i >> 1) ? 16 : 0);
                #pragma unroll
                for (int h = 0; h < 4; h++)
                    atomicAdd(&ss[row * 4 + h], sp[i][h]);
            }
        }
    }
    __syncthreads();   // scores complete; pipeline region dead

    // kick Wc fp16 image into smem (overlaps softmax + pooling)
    {
        #pragma unroll
        for (int it = 0; it < 16; it++) {
            const int q = it * 256 + tid;              // 4096 x 16B
            const int row = q >> 3, seg = q & 7;
            cp16cg(sbase + row * 128 + seg * 16, g_Wc16 + (size_t)row * NCLP + seg * 8);
        }
        CP_COMMIT();
    }

    // per-bag softmax: thread = (row, head)
    {
        const int r = tid >> 2;
        const int h = tid & 3;
        const int b0 = r & ~15;
        float m = -1e30f;
        #pragma unroll
        for (int q = 0; q < BAGSZ; q++) m = fmaxf(m, ss[(b0 + q) * 4 + h]);
        float den = 0.f;
        #pragma unroll
        for (int q = 0; q < BAGSZ; q++) den += __expf(ss[(b0 + q) * 4 + h] - m);
        float a = __expf(ss[r * 4 + h] - m) * __frcp_rn(den);
        a += __shfl_xor_sync(0xFFFFFFFF, a, 1);
        a += __shfl_xor_sync(0xFFFFFFFF, a, 2);
        if (h == 0) wr[r] = a * 0.25f;
    }
    __syncthreads();

    // pooling: thread owns (bag, 8-dim block)
    {
        const int bag = tid >> 6;
        const int d0  = (tid & 63) * 8;
        float a0 = 0.f, a1 = 0.f, a2 = 0.f, a3 = 0.f;
        float a4 = 0.f, a5 = 0.f, a6 = 0.f, a7 = 0.f;
        #pragma unroll 4
        for (int q = 0; q < BAGSZ; q++) {
            const int rr = bag * BAGSZ + q;
            const float w = wr[rr];
            const float* src = x + (size_t)(row0 + rr) * DIM + d0;
            const float4 v0 = *(const float4*)src;
            const float4 v1 = *(const float4*)(src + 4);
            a0 += w * v0.x; a1 += w * v0.y; a2 += w * v0.z; a3 += w * v0.w;
            a4 += w * v1.x; a5 += w * v1.y; a6 += w * v1.z; a7 += w * v1.w;
        }
        *(float4*)&repr[bag * DIM + d0]     = make_float4(a0, a1, a2, a3);
        *(float4*)&repr[bag * DIM + d0 + 4] = make_float4(a4, a5, a6, a7);
    }
    CP_WAIT0();
    __syncthreads();   // repr + wch ready

    // classifier: thread owns 2 classes x 64-k segment x 4 bags
    {
        const int cls2 = (tid & 31) * 2;
        const int seg  = tid >> 5;
        float b0a = 0.f, b0b = 0.f, b1a = 0.f, b1b = 0.f;
        float b2a = 0.f, b2b = 0.f, b3a = 0.f, b3b = 0.f;
        const int k0 = seg * 64;
        #pragma unroll 8
        for (int k = 0; k < 64; k++) {
            const __half2 wv = *(const __half2*)&wch[(k0 + k) * NCLP + cls2];
            const float wa = __half2float(__low2half(wv));
            const float wb = __half2float(__high2half(wv));
            const float r0 = repr[0 * DIM + k0 + k];
            const float r1 = repr[1 * DIM + k0 + k];
            const float r2 = repr[2 * DIM + k0 + k];
            const float r3 = repr[3 * DIM + k0 + k];
            b0a += r0 * wa; b0b += r0 * wb;
            b1a += r1 * wa; b1b += r1 * wb;
            b2a += r2 * wa; b2b += r2 * wb;
            b3a += r3 * wa; b3b += r3 * wb;
        }
        float* p = part + seg * 256;
        p[0 * 64 + cls2] = b0a; p[0 * 64 + cls2 + 1] = b0b;
        p[1 * 64 + cls2] = b1a; p[1 * 64 + cls2 + 1] = b1b;
        p[2 * 64 + cls2] = b2a; p[2 * 64 + cls2 + 1] = b2b;
        p[3 * 64 + cls2] = b3a; p[3 * 64 + cls2 + 1] = b3b;
    }
    __syncthreads();

    // reduce 8 segments, add bias, store
    {
        const int bag = tid >> 6;
        const int cls = tid & 63;
        if (cls < NCLS) {
            float s = 0.f;
            #pragma unroll
            for (int g = 0; g < 8; g++) s += part[g * 256 + bag * 64 + cls];
            const int bag_g = blockIdx.x * (TM / BAGSZ) + bag;
            out[(size_t)bag_g * NCLS + cls] = s + bc[cls];
        }
    }
}

extern "C" void kernel_launch(void* const* d_in, const int* in_sizes, int n_in,
                              void* d_out, int out_size)
{
    const float* x  = (const float*)d_in[0];
    const float* W1 = (const float*)d_in[1];
    const float* W2 = (const float*)d_in[2];
    const float* Wc = (const float*)d_in[3];
    const float* bc = (const float*)d_in[4];
    float* out = (float*)d_out;

    cudaFuncSetAttribute(mlssa_main,
                         cudaFuncAttributeMaxDynamicSharedMemorySize, SMEM_TOTAL);

    prep_kernel<<<640, 256>>>(W1, Wc);
    mlssa_main<<<NTOT / TM, 256, SMEM_TOTAL>>>(x, W2, bc, out);
}

// round 16
// speedup vs baseline: 1.1188x; 1.0277x over previous
#include <cuda_runtime.h>
#include <cuda_fp16.h>
#include <math.h>
#include <cstdint>
#include <string.h>

#define NTOT   131072
#define DIM    512
#define DATT   256
#define NHEAD  4
#define NCLS   53
#define NCLP   64
#define BAGSZ  16
#define NBAGS  8192

#define TM     64            // rows per block (4 bags); grid 2048
#define KC     32            // K chunk
#define NCHUNK (DIM / KC)    // 16
#define NSTAGE 4
#define A_STRIDE 80          // bytes/row (32 fp16 + 8 pad)
#define B_STRIDE 528         // bytes/row (256 fp16 + 8 pad)

// stage layout (bytes): A 64*80=5120 | B 32*528=16896
#define STAGE_SZ 22016
#define A_OFF    0
#define B_OFF    5120
#define PIPE_SZ  (NSTAGE * STAGE_SZ)      // 88064

// union region [0, PIPE_SZ): pipeline -> Wc fp16 image (65536) post-GEMM
#define OFF_W2    PIPE_SZ                 // 4096
#define OFF_SS    (OFF_W2 + 4096)         // 1024
#define OFF_WR    (OFF_SS + 1024)         // 256
#define OFF_REPR  (OFF_WR + 256)          // 8192 (4 bags x 512 f32)
#define OFF_PART  (OFF_REPR + 8192)       // 8192 (score slices / cls partials)
#define SMEM_TOTAL (OFF_PART + 8192)      // 109824 -> 2 CTAs/SM

__device__ __align__(16) __half g_Wpk[DIM * DATT];     // W1 fp16, k-major
__device__ __align__(16) __half g_Wc16[DIM * NCLP];    // Wc fp16, [k][64] padded

extern __shared__ char smem_raw[];

__device__ __forceinline__ uint32_t smem_u32(const void* p) {
    uint32_t a;
    asm("{ .reg .u64 t; cvta.to.shared.u64 t, %1; cvt.u32.u64 %0, t; }" : "=r"(a) : "l"(p));
    return a;
}
// L1-bypass (L2 -> smem) 16B async copy
__device__ __forceinline__ void cp16cg(uint32_t dst, const void* src) {
    asm volatile("cp.async.cg.shared.global [%0], [%1], 16;" :: "r"(dst), "l"(src));
}
#define CP_COMMIT() asm volatile("cp.async.commit_group;" ::: "memory")
#define CP_WAIT2()  asm volatile("cp.async.wait_group 2;" ::: "memory")
#define CP_WAIT1()  asm volatile("cp.async.wait_group 1;" ::: "memory")
#define CP_WAIT0()  asm volatile("cp.async.wait_group 0;" ::: "memory")

__device__ __forceinline__ void ldsm_x4(uint32_t* r, uint32_t addr) {
    asm volatile("ldmatrix.sync.aligned.m8n8.x4.shared.b16 {%0,%1,%2,%3}, [%4];"
        : "=r"(r[0]), "=r"(r[1]), "=r"(r[2]), "=r"(r[3]) : "r"(addr));
}
__device__ __forceinline__ void ldsm_x4_t(uint32_t* r, uint32_t addr) {
    asm volatile("ldmatrix.sync.aligned.m8n8.x4.trans.shared.b16 {%0,%1,%2,%3}, [%4];"
        : "=r"(r[0]), "=r"(r[1]), "=r"(r[2]), "=r"(r[3]) : "r"(addr));
}
__device__ __forceinline__ void mma16816(float* d, const uint32_t* a,
                                         uint32_t b0, uint32_t b1) {
    asm volatile(
        "mma.sync.aligned.m16n8k16.row.col.f32.f16.f16.f32 "
        "{%0,%1,%2,%3}, {%4,%5,%6,%7}, {%8,%9}, {%0,%1,%2,%3};"
        : "+f"(d[0]), "+f"(d[1]), "+f"(d[2]), "+f"(d[3])
        : "r"(a[0]), "r"(a[1]), "r"(a[2]), "r"(a[3]), "r"(b0), "r"(b1));
}

__device__ __forceinline__ float fast_tanh(float v) {
    const float a = fabsf(v);
    const float e = __expf(-2.0f * a);
    const float t = (1.0f - e) * __frcp_rn(1.0f + e);
    return copysignf(t, v);
}

// merged one-time prep
__global__ void prep_kernel(const float* __restrict__ W1, const float* __restrict__ Wc) {
    if (blockIdx.x < 512) {
        const int idx = blockIdx.x * 256 + threadIdx.x;
        g_Wpk[idx] = __float2half(W1[idx]);
    } else {
        const int idx = (blockIdx.x - 512) * 256 + threadIdx.x;
        const int k = idx >> 6, c = idx & 63;
        g_Wc16[idx] = (c < NCLS) ? __float2half(Wc[k * NCLS + c]) : __float2half(0.f);
    }
}

__device__ __forceinline__ void issue_b(int c, uint32_t sbase, int tid) {
    const uint32_t dst0 = sbase + (c & (NSTAGE - 1)) * STAGE_SZ + B_OFF;
    const __half* src0 = g_Wpk + (size_t)c * (KC * DATT);
    #pragma unroll
    for (int it = 0; it < 4; it++) {
        const int q = it * 256 + tid;
        const int row = q >> 5, seg = q & 31;
        cp16cg(dst0 + row * B_STRIDE + seg * 16, src0 + row * DATT + seg * 8);
    }
    CP_COMMIT();
}

__device__ __forceinline__ void ld_a(const float* __restrict__ x, int row0,
                                     int c, int tid, float4& v0, float4& v1) {
    const int row = tid >> 2, cg = tid & 3;
    const float* src = x + (size_t)(row0 + row) * DIM + c * KC + cg * 8;
    v0 = *(const float4*)src;
    v1 = *(const float4*)(src + 4);
}
__device__ __forceinline__ void st_a(int c, uint32_t sbase, int tid,
                                     float4 v0, float4 v1) {
    const int row = tid >> 2, cg = tid & 3;
    const uint32_t base = sbase + (c & (NSTAGE - 1)) * STAGE_SZ + A_OFF
                        + row * A_STRIDE + cg * 16;
    __half h0 = __float2half(v0.x), h1 = __float2half(v0.y);
    __half h2 = __float2half(v0.z), h3 = __float2half(v0.w);
    __half h4 = __float2half(v1.x), h5 = __float2half(v1.y);
    __half h6 = __float2half(v1.z), h7 = __float2half(v1.w);
    uint4 hv = make_uint4(
        (uint32_t)__half_as_ushort(h0) | ((uint32_t)__half_as_ushort(h1) << 16),
        (uint32_t)__half_as_ushort(h2) | ((uint32_t)__half_as_ushort(h3) << 16),
        (uint32_t)__half_as_ushort(h4) | ((uint32_t)__half_as_ushort(h5) << 16),
        (uint32_t)__half_as_ushort(h6) | ((uint32_t)__half_as_ushort(h7) << 16));
    asm volatile("st.shared.v4.b32 [%0], {%1,%2,%3,%4};" ::
        "r"(base), "r"(hv.x), "r"(hv.y), "r"(hv.z), "r"(hv.w));
}

__global__ __launch_bounds__(256, 2)
void mlssa_main(const float* __restrict__ x, const float* __restrict__ W2,
                const float* __restrict__ bc, float* __restrict__ out)
{
    const int tid  = threadIdx.x;
    const int wid  = tid >> 5;
    const int lane = tid & 31;
    const int row0 = blockIdx.x * TM;
    const uint32_t sbase = smem_u32(smem_raw);

    __half* wch  = (__half*)(smem_raw);           // overlays pipeline post-GEMM
    float*  w2s  = (float*)(smem_raw + OFF_W2);
    float*  ss   = (float*)(smem_raw + OFF_SS);
    float*  wr   = (float*)(smem_raw + OFF_WR);
    float*  repr = (float*)(smem_raw + OFF_REPR);
    float*  part = (float*)(smem_raw + OFF_PART);

    // prologue: stage chunks 0..2; prefetch chunk 3 into regs
    issue_b(0, sbase, tid);
    issue_b(1, sbase, tid);
    issue_b(2, sbase, tid);
    {
        float4 a0, a1;
        ld_a(x, row0, 0, tid, a0, a1); st_a(0, sbase, tid, a0, a1);
        ld_a(x, row0, 1, tid, a0, a1); st_a(1, sbase, tid, a0, a1);
        ld_a(x, row0, 2, tid, a0, a1); st_a(2, sbase, tid, a0, a1);
    }
    float4 rA0, rA1;
    ld_a(x, row0, 3, tid, rA0, rA1);

    for (int i = tid; i < DATT * NHEAD; i += 256) w2s[i] = W2[i];

    const int warp_m = wid >> 2;   // 2(M) x 4(N), warp tile 32x64
    const int warp_n = wid & 3;

    const uint32_t aoff = (uint32_t)(warp_m * 32 + (lane & 15)) * A_STRIDE
                        + (uint32_t)(lane >> 4) * 16;
    const uint32_t boff = (uint32_t)(((lane >> 3) & 1) * 8 + (lane & 7)) * B_STRIDE
                        + (uint32_t)(warp_n * 64 + (lane >> 4) * 8) * 2;

    float acc[2][8][4];
    #pragma unroll
    for (int i = 0; i < 2; i++)
        #pragma unroll
        for (int j = 0; j < 8; j++)
            #pragma unroll
            for (int k = 0; k < 4; k++) acc[i][j][k] = 0.0f;

    for (int c = 0; c < NCHUNK; c++) {
        if (c < NCHUNK - 2)       { CP_WAIT2(); }
        else if (c == NCHUNK - 2) { CP_WAIT1(); }
        else                      { CP_WAIT0(); }
        __syncthreads();   // chunk c visible; stage (c+3)&3 dead

        if (c + 3 < NCHUNK) {
            st_a(c + 3, sbase, tid, rA0, rA1);
            issue_b(c + 3, sbase, tid);
            if (c + 4 < NCHUNK) ld_a(x, row0, c + 4, tid, rA0, rA1);
        }

        const uint32_t stg = sbase + (c & (NSTAGE - 1)) * STAGE_SZ;
        const uint32_t sA = stg + A_OFF + aoff;
        const uint32_t sB = stg + B_OFF + boff;

        #pragma unroll
        for (int ks = 0; ks < 2; ks++) {
            uint32_t afr[2][4];
            ldsm_x4(afr[0], sA + ks * 32);
            ldsm_x4(afr[1], sA + 16 * A_STRIDE + ks * 32);
            #pragma unroll
            for (int g = 0; g < 4; g++) {
                uint32_t bfr[4];
                ldsm_x4_t(bfr, sB + ks * 16 * B_STRIDE + g * 32);
                #pragma unroll
                for (int mi = 0; mi < 2; mi++) {
                    mma16816(acc[mi][g * 2 + 0], afr[mi], bfr[0], bfr[1]);
                    mma16816(acc[mi][g * 2 + 1], afr[mi], bfr[2], bfr[3]);
                }
            }
        }
    }

    // ---- fragment-direct epilogue: tanh + W2 projection, atomic-free ----
    {
        float sp[4][4];
        #pragma unroll
        for (int i = 0; i < 4; i++)
            #pragma unroll
            for (int h = 0; h < 4; h++) sp[i][h] = 0.0f;

        const int cb0 = warp_n * 64 + (lane & 3) * 2;
        #pragma unroll
        for (int nj = 0; nj < 8; nj++) {
            const float4 wv0 = *(const float4*)&w2s[(cb0 + nj * 8) * 4];
            const float4 wv1 = *(const float4*)&w2s[(cb0 + nj * 8 + 1) * 4];
            #pragma unroll
            for (int mi = 0; mi < 2; mi++) {
                const float t0 = fast_tanh(acc[mi][nj][0]);
                const float t1 = fast_tanh(acc[mi][nj][1]);
                const float t2 = fast_tanh(acc[mi][nj][2]);
                const float t3 = fast_tanh(acc[mi][nj][3]);
                sp[mi*2+0][0] += t0 * wv0.x + t1 * wv1.x;
                sp[mi*2+0][1] += t0 * wv0.y + t1 * wv1.y;
                sp[mi*2+0][2] += t0 * wv0.z + t1 * wv1.z;
                sp[mi*2+0][3] += t0 * wv0.w + t1 * wv1.w;
                sp[mi*2+1][0] += t2 * wv0.x + t3 * wv1.x;
                sp[mi*2+1][1] += t2 * wv0.y + t3 * wv1.y;
                sp[mi*2+1][2] += t2 * wv0.z + t3 * wv1.z;
                sp[mi*2+1][3] += t2 * wv0.w + t3 * wv1.w;
            }
        }
        #pragma unroll
        for (int i = 0; i < 4; i++)
            #pragma unroll
            for (int h = 0; h < 4; h++) {
                sp[i][h] += __shfl_xor_sync(0xFFFFFFFF, sp[i][h], 1);
                sp[i][h] += __shfl_xor_sync(0xFFFFFFFF, sp[i][h], 2);
            }
        // leaders store into per-warp_n slice of part: [warp_n][row][head]
        if ((lane & 3) == 0) {
            const int rbase = warp_m * 32 + (lane >> 2);
            float* slice = part + warp_n * 256;
            #pragma unroll
            for (int i = 0; i < 4; i++) {
                const int row = rbase + ((i & 1) ? 8 : 0) + ((i >> 1) ? 16 : 0);
                *(float4*)&slice[row * 4] =
                    make_float4(sp[i][0], sp[i][1], sp[i][2], sp[i][3]);
            }
        }
    }
    __syncthreads();

    // reduce 4 warp_n slices -> ss[row][head] (thread = (row, head))
    ss[tid] = part[tid] + part[256 + tid] + part[512 + tid] + part[768 + tid];
    __syncthreads();   // scores complete; pipeline region dead

    // kick Wc fp16 image into smem (overlaps softmax + pooling)
    {
        #pragma unroll
        for (int it = 0; it < 16; it++) {
            const int q = it * 256 + tid;              // 4096 x 16B
            const int row = q >> 3, seg = q & 7;
            cp16cg(sbase + row * 128 + seg * 16, g_Wc16 + (size_t)row * NCLP + seg * 8);
        }
        CP_COMMIT();
    }

    // per-bag softmax: thread = (row, head)
    {
        const int r = tid >> 2;
        const int h = tid & 3;
        const int b0 = r & ~15;
        float m = -1e30f;
        #pragma unroll
        for (int q = 0; q < BAGSZ; q++) m = fmaxf(m, ss[(b0 + q) * 4 + h]);
        float den = 0.f;
        #pragma unroll
        for (int q = 0; q < BAGSZ; q++) den += __expf(ss[(b0 + q) * 4 + h] - m);
        float a = __expf(ss[r * 4 + h] - m) * __frcp_rn(den);
        a += __shfl_xor_sync(0xFFFFFFFF, a, 1);
        a += __shfl_xor_sync(0xFFFFFFFF, a, 2);
        if (h == 0) wr[r] = a * 0.25f;
    }
    __syncthreads();

    // pooling: thread owns (bag, 8-dim block)
    {
        const int bag = tid >> 6;
        const int d0  = (tid & 63) * 8;
        float a0 = 0.f, a1 = 0.f, a2 = 0.f, a3 = 0.f;
        float a4 = 0.f, a5 = 0.f, a6 = 0.f, a7 = 0.f;
        #pragma unroll 4
        for (int q = 0; q < BAGSZ; q++) {
            const int rr = bag * BAGSZ + q;
            const float w = wr[rr];
            const float* src = x + (size_t)(row0 + rr) * DIM + d0;
            const float4 v0 = *(const float4*)src;
            const float4 v1 = *(const float4*)(src + 4);
            a0 += w * v0.x; a1 += w * v0.y; a2 += w * v0.z; a3 += w * v0.w;
            a4 += w * v1.x; a5 += w * v1.y; a6 += w * v1.z; a7 += w * v1.w;
        }
        *(float4*)&repr[bag * DIM + d0]     = make_float4(a0, a1, a2, a3);
        *(float4*)&repr[bag * DIM + d0 + 4] = make_float4(a4, a5, a6, a7);
    }
    CP_WAIT0();
    __syncthreads();   // repr + wch ready

    // classifier: thread owns 2 classes x 64-k segment x 4 bags
    {
        const int cls2 = (tid & 31) * 2;
        const int seg  = tid >> 5;
        float b0a = 0.f, b0b = 0.f, b1a = 0.f, b1b = 0.f;
        float b2a = 0.f, b2b = 0.f, b3a = 0.f, b3b = 0.f;
        const int k0 = seg * 64;
        #pragma unroll 8
        for (int k = 0; k < 64; k++) {
            const __half2 wv = *(const __half2*)&wch[(k0 + k) * NCLP + cls2];
            const float wa = __half2float(__low2half(wv));
            const float wb = __half2float(__high2half(wv));
            const float r0 = repr[0 * DIM + k0 + k];
            const float r1 = repr[1 * DIM + k0 + k];
            const float r2 = repr[2 * DIM + k0 + k];
            const float r3 = repr[3 * DIM + k0 + k];
            b0a += r0 * wa; b0b += r0 * wb;
            b1a += r1 * wa; b1b += r1 * wb;
            b2a += r2 * wa; b2b += r2 * wb;
            b3a += r3 * wa; b3b += r3 * wb;
        }
        float* p = part + seg * 256;
        p[0 * 64 + cls2] = b0a; p[0 * 64 + cls2 + 1] = b0b;
        p[1 * 64 + cls2] = b1a; p[1 * 64 + cls2 + 1] = b1b;
        p[2 * 64 + cls2] = b2a; p[2 * 64 + cls2 + 1] = b2b;
        p[3 * 64 + cls2] = b3a; p[3 * 64 + cls2 + 1] = b3b;
    }
    __syncthreads();

    // reduce 8 segments, add bias, store
    {
        const int bag = tid >> 6;
        const int cls = tid & 63;
        if (cls < NCLS) {
            float s = 0.f;
            #pragma unroll
            for (int g = 0; g < 8; g++) s += part[g * 256 + bag * 64 + cls];
            const int bag_g = blockIdx.x * (TM / BAGSZ) + bag;
            out[(size_t)bag_g * NCLS + cls] = s + bc[cls];
        }
    }
}

extern "C" void kernel_launch(void* const* d_in, const int* in_sizes, int n_in,
                              void* d_out, int out_size)
{
    const float* x  = (const float*)d_in[0];
    const float* W1 = (const float*)d_in[1];
    const float* W2 = (const float*)d_in[2];
    const float* Wc = (const float*)d_in[3];
    const float* bc = (const float*)d_in[4];
    float* out = (float*)d_out;

    cudaFuncSetAttribute(mlssa_main,
                         cudaFuncAttributeMaxDynamicSharedMemorySize, SMEM_TOTAL);

    prep_kernel<<<640, 256>>>(W1, Wc);
    mlssa_main<<<NTOT / TM, 256, SMEM_TOTAL>>>(x, W2, bc, out);
}